// round 14
// baseline (speedup 1.0000x reference)
#include <cuda_runtime.h>
#include <cuda_bf16.h>

#define NV 16384   // 128*128 voxels
#define NT 64      // time samples
typedef unsigned long long ULL;

// ---------------- device scratch (static, allocation-free) ----------------
__device__ float g_ctcdc[NT * NV];                 // [m][voxel], coalesced
__device__ __align__(16) float g_aifpad[576];      // phys[63+i] = aif_os[i], zero pad
__device__ __align__(16) float g_tsh[512];
__device__ __align__(16) float g_step[512];
__device__ float g_partCdc[64];
__device__ float g_partCnn[3 * 64];
__device__ float g_consts[4];                      // rscale, 2*sp_lam/C_nn[0..2]

// jax.image.resize(method='linear') upsample 64->512: half-pixel centers,
// renormalized (clamped) edges.
__device__ __forceinline__ float interp64(const float* __restrict__ x, int o) {
    float p = (o + 0.5f) * 0.125f - 0.5f;
    if (p <= 0.0f)  return x[0];
    if (p >= 63.0f) return x[63];
    int i = (int)p;              // p > 0 -> trunc == floor
    float f = p - (float)i;
    return (1.0f - f) * x[i] + f * x[i + 1];
}

// ---------------- kernel A: static 1-D tables ----------------
__global__ void k_static(const float* __restrict__ aif, const float* __restrict__ time_) {
    int o = threadIdx.x;                 // 576 threads
    g_aifpad[o] = 0.0f;
    __syncthreads();
    if (o < 512) {
        float ab = (aif[0] + aif[1] + aif[2] + aif[3] + aif[4]) / 5.0f;
        g_aifpad[63 + o] = interp64(aif, o) - ab;
        float t16 = interp64(time_, 16);           // t_os[NEG_SHIFT]
        float tsh = interp64(time_, o) - t16;
        g_tsh[o] = tsh;
        float e = __expf(-500.0f * tsh);
        g_step[o] = __fdividef(1.0f, 1.0f + e);
    }
}

// ---------------- kernel B: per-voxel ctc_dc + partial reductions ----------------
__global__ void k_voxprep(const float* __restrict__ ctc, const float* __restrict__ eta) {
    int v = blockIdx.x * 256 + threadIdx.x;
    float c[NT];
    const float4* p4 = reinterpret_cast<const float4*>(ctc) + (size_t)v * 16;
#pragma unroll
    for (int i = 0; i < 16; ++i) {
        float4 q = p4[i];
        c[4*i+0] = q.x; c[4*i+1] = q.y; c[4*i+2] = q.z; c[4*i+3] = q.w;
    }
    float base = (c[0] + c[1] + c[2] + c[3] + c[4]) / 5.0f;
    float s2;
    {
        float cd = c[0] - base;              // m = 0 : clamped edge sample
        g_ctcdc[v] = cd;
        s2 = cd * cd;
    }
#pragma unroll
    for (int m = 1; m < NT; ++m) {           // interior: 0.4375*c[m-1] + 0.5625*c[m]
        float cd = 0.4375f * c[m-1] + 0.5625f * c[m] - base;
        g_ctcdc[m * NV + v] = cd;
        s2 += cd * cd;
    }
    float e0 = eta[v], e1 = eta[NV + v], e2 = eta[2*NV + v];
    __shared__ float4 sm[256];
    sm[threadIdx.x] = make_float4(s2, e0*e0, e1*e1, e2*e2);
    __syncthreads();
    for (int s = 128; s > 0; s >>= 1) {      // fixed-order tree -> deterministic
        if (threadIdx.x < s) {
            float4 a = sm[threadIdx.x], b = sm[threadIdx.x + s];
            sm[threadIdx.x] = make_float4(a.x+b.x, a.y+b.y, a.z+b.z, a.w+b.w);
        }
        __syncthreads();
    }
    if (threadIdx.x == 0) {
        float4 r = sm[0];
        g_partCdc[blockIdx.x]        = r.x;
        g_partCnn[blockIdx.x]        = r.y;
        g_partCnn[64  + blockIdx.x]  = r.z;
        g_partCnn[128 + blockIdx.x]  = r.w;
    }
}

// ---------------- kernel C: final reduce + constants ----------------
__global__ void k_consts(const float* __restrict__ lam) {
    int t = threadIdx.x;                     // 64 threads
    __shared__ float4 sm[64];
    sm[t] = make_float4(g_partCdc[t], g_partCnn[t], g_partCnn[64 + t], g_partCnn[128 + t]);
    __syncthreads();
    for (int s = 32; s > 0; s >>= 1) {
        if (t < s) {
            float4 a = sm[t], b = sm[t + s];
            sm[t] = make_float4(a.x+b.x, a.y+b.y, a.z+b.z, a.w+b.w);
        }
        __syncthreads();
    }
    if (t == 0) {
        float Cdc = sm[0].x;
        float x = lam[0];
        float sp = fmaxf(x, 0.0f) + log1pf(expf(-fabsf(x)));   // stable softplus
        g_consts[0] = 0.25f / Cdc;             // r[m] = (est/8 - cd) * 2/(8*Cdc)
        g_consts[1] = 2.0f * sp / sm[0].y;
        g_consts[2] = 2.0f * sp / sm[0].z;
        g_consts[3] = 2.0f * sp / sm[0].w;
    }
}

// ---------------- packed fp32x2 helpers (sm_103a) ----------------
__device__ __forceinline__ ULL pack2(float lo, float hi) {
    ULL r; asm("mov.b64 %0, {%1, %2};" : "=l"(r) : "f"(lo), "f"(hi)); return r;
}
__device__ __forceinline__ float2 unpack2(ULL v) {
    float2 r; asm("mov.b64 {%0, %1}, %2;" : "=f"(r.x), "=f"(r.y) : "l"(v)); return r;
}
__device__ __forceinline__ void ffma2(ULL& d, ULL a, ULL b) {
    asm("fma.rn.f32x2 %0, %1, %2, %0;" : "+l"(d) : "l"(a), "l"(b));
}

// ---------------- kernel D: 10 GD iterations, 2 threads per voxel ----------------
// FORWARD: row-parity split (thread p owns rows m = 2*lm+p, acc = 32 packed regs),
// iterated DIAGONALLY: window index u = 2*lm - 8g - q, window float base
// 56+8p+8u.  Each window is loaded once per 4-octet half and feeds the 2 rows
// whose octet parity matches u (8 FFMA2 per load).  u <= -2 windows lie wholly
// in the zero pad -> skipped (exact zeros).
// ADJOINT: octet-parity split with R11's (verified) diagonal: window t = m-M0-2j
// at float base 56-8p+8t feeds up to NJ octet accumulators; rm held as floats,
// packed per-use.
__global__ __launch_bounds__(256, 1)
void k_main(const float* __restrict__ eta_in, float* __restrict__ out) {
    __shared__ __align__(16) float s_aif[576];
    __shared__ __align__(16) float s_tsh[512];
    __shared__ __align__(16) float s_step[512];
    __shared__ float s_ex[128 * 65];     // [t0][m], padded: conflict-free both axes
    __shared__ float s_red[2][128][4];   // partial gradient sums
    __shared__ float s_c[4];
    int tid = threadIdx.x;
    for (int i = tid; i < 576; i += 256) s_aif[i] = g_aifpad[i];
    for (int i = tid; i < 512; i += 256) { s_tsh[i] = g_tsh[i]; s_step[i] = g_step[i]; }
    if (tid < 4) s_c[tid] = g_consts[tid];
    __syncthreads();

    const int t0 = tid & 127;
    const int p  = tid >> 7;
    const int v  = blockIdx.x * 128 + t0;

    // forward windows: float base 56+8p+8u -> ULL base 28+4p+4u
    const ULL* wbF = reinterpret_cast<const ULL*>(s_aif) + 28 + 4 * p;
    // adjoint windows: float base 56-8p+8t -> ULL base 28-4p+4t
    const ULL* wbA = reinterpret_cast<const ULL*>(s_aif) + 28 - 4 * p;

    float pA = eta_in[v], pk = eta_in[NV + v], pt = eta_in[2*NV + v];
    float A = pA, k = pk, tz = pt;
    const float rscale = s_c[0], rlA = s_c[1], rlk = s_c[2], rlt = s_c[3];

#pragma unroll 1
    for (int it = 0; it < 10; ++it) {
        float kt0 = k * tz;

        // ========== forward: rows m = 2*lm + p, diagonal windows ==========
        ULL acc2[32];
#pragma unroll
        for (int lm = 0; lm < 32; ++lm) acc2[lm] = 0ULL;

#pragma unroll
        for (int g = 0; g < 8; ++g) {
            const int NO = (g == 7) ? 6 : 8;      // octets in group
#pragma unroll
            for (int h = 0; h < 2; ++h) {
                const int NH = (NO - 4*h < 4) ? (NO - 4*h) : 4;
                // ---- ir packs for this half's octets ----
                ULL I[4][4];
#pragma unroll
                for (int r = 0; r < 4; ++r) {
                    if (r < NH) {                 // compile-time
                        const int lb = 16 + 64 * g + 8 * (4*h + r);
                        float4 ts0 = *reinterpret_cast<const float4*>(&s_tsh[lb]);
                        float4 ts1 = *reinterpret_cast<const float4*>(&s_tsh[lb + 4]);
                        float4 st0 = *reinterpret_cast<const float4*>(&s_step[lb]);
                        float4 st1 = *reinterpret_cast<const float4*>(&s_step[lb + 4]);
                        float tshv[8] = {ts0.x,ts0.y,ts0.z,ts0.w,ts1.x,ts1.y,ts1.z,ts1.w};
                        float stv[8]  = {st0.x,st0.y,st0.z,st0.w,st1.x,st1.y,st1.z,st1.w};
                        float irv[8];
#pragma unroll
                        for (int i = 0; i < 8; ++i) {
                            float x = kt0 - k * tshv[i];
                            float e = __expf(-x);
                            float s = __fdividef(1.0f, 1.0f + e);
                            irv[i] = A * s * stv[i];
                        }
                        I[r][0] = pack2(irv[7], irv[6]);  // lowest window float = l = lb+7
                        I[r][1] = pack2(irv[5], irv[4]);
                        I[r][2] = pack2(irv[3], irv[2]);
                        I[r][3] = pack2(irv[1], irv[0]);
                    }
                }
                const int u_hi = 62 - 8 * g - 4 * h;
#pragma unroll
                for (int u = -1; u <= u_hi; ++u) {
                    ulonglong2 qa = *reinterpret_cast<const ulonglong2*>(wbF + 4*u);
                    ulonglong2 qb = *reinterpret_cast<const ulonglong2*>(wbF + 4*u + 2);
                    const int q0 = (u & 1);       // octet parity matching u
#pragma unroll
                    for (int rr = 0; rr < 2; ++rr) {
                        const int ri = q0 + 2 * rr;          // index within half
                        if (ri < NH) {                        // compile-time
                            const int q  = 4 * h + ri;
                            const int lm = (u + 8 * g + q) >> 1;  // exact, >= 4g
                            if (lm < 32) {                    // compile-time
                                ffma2(acc2[lm], I[ri][0], qa.x);
                                ffma2(acc2[lm], I[ri][1], qa.y);
                                ffma2(acc2[lm], I[ri][2], qb.x);
                                ffma2(acc2[lm], I[ri][3], qb.y);
                            }
                        }
                    }
                }
            }
        }

        // residual for my rows (complete, no combine needed)
#pragma unroll
        for (int lm = 0; lm < 32; ++lm) {
            const int m = 2 * lm + p;
            float2 u = unpack2(acc2[lm]);
            float full = u.x + u.y;
            float cd = __ldg(&g_ctcdc[m * NV + v]);      // L1-resident after iter 1
            s_ex[t0 * 65 + m] = (0.125f * full - cd) * rscale;
        }
        __syncthreads();

        // rm into registers (acc2 dead -> regs free)
        float rmv[NT];
#pragma unroll
        for (int m = 0; m < NT; ++m) rmv[m] = s_ex[t0 * 65 + m];

        // ========== adjoint: diagonal windows, my parity's octets ==========
        float sumA = 0.0f, sumG = 0.0f, sumGT = 0.0f;
#pragma unroll
        for (int g = 0; g < 8; ++g) {
            const int M0 = 8 * g;
            const int NJ = (g == 7) ? 3 : 4;
            const int N  = 64 - M0;
            ULL w[4][4];
#pragma unroll
            for (int j = 0; j < 4; ++j)
#pragma unroll
                for (int q = 0; q < 4; ++q) w[j][q] = 0ULL;

#pragma unroll
            for (int t = 0; t < N; ++t) {
                ulonglong2 qa = *reinterpret_cast<const ulonglong2*>(wbA + 4*t);
                ulonglong2 qb = *reinterpret_cast<const ulonglong2*>(wbA + 4*t + 2);
#pragma unroll
                for (int j = 0; j < 4; ++j) {
                    if (j < NJ) {                       // compile-time
                        const int n = t + 2 * j;
                        if (n < N) {                    // compile-time
                            float r = rmv[M0 + n];
                            ULL r2 = pack2(r, r);
                            ffma2(w[j][0], r2, qa.x);
                            ffma2(w[j][1], r2, qa.y);
                            ffma2(w[j][2], r2, qb.x);
                            ffma2(w[j][3], r2, qb.y);
                        }
                    }
                }
            }
#pragma unroll
            for (int j = 0; j < 4; ++j) {
                if (j < NJ) {
                    float2 u0 = unpack2(w[j][0]), u1 = unpack2(w[j][1]),
                           u2 = unpack2(w[j][2]), u3 = unpack2(w[j][3]);
                    float wv[8] = {u3.y, u3.x, u2.y, u2.x, u1.y, u1.x, u0.y, u0.x};
                    const int lb = 16 + 64 * g + 8 * (2 * j) + 8 * p + 8 * 0 + 8 * j * 0
                                   + 8 * j;            // lb = 16+64g+16j+8p
                    // (written explicitly below to avoid confusion)
                    const int lbx = 16 + 64 * g + 16 * j + 8 * p;
                    (void)lb;
                    float4 ts0 = *reinterpret_cast<const float4*>(&s_tsh[lbx]);
                    float4 ts1 = *reinterpret_cast<const float4*>(&s_tsh[lbx + 4]);
                    float4 st0 = *reinterpret_cast<const float4*>(&s_step[lbx]);
                    float4 st1 = *reinterpret_cast<const float4*>(&s_step[lbx + 4]);
                    float tshv[8] = {ts0.x,ts0.y,ts0.z,ts0.w,ts1.x,ts1.y,ts1.z,ts1.w};
                    float stv[8]  = {st0.x,st0.y,st0.z,st0.w,st1.x,st1.y,st1.z,st1.w};
#pragma unroll
                    for (int i = 0; i < 8; ++i) {
                        float tshl = tshv[i];
                        float x = kt0 - k * tshl;
                        float e = __expf(-x);
                        float s = __fdividef(1.0f, 1.0f + e);
                        float u = wv[i] * stv[i];
                        sumA = fmaf(u, s, sumA);             // dir/dA = s*step
                        float gg = u * A * s * (1.0f - s);
                        sumG += gg;
                        sumGT = fmaf(gg, tshl, sumGT);
                    }
                }
            }
        }

        // ---------- combine partial sums across the two parts ----------
        s_red[p][t0][0] = sumA; s_red[p][t0][1] = sumG; s_red[p][t0][2] = sumGT;
        __syncthreads();
        sumA  += s_red[1 - p][t0][0];   // a+b == b+a bitwise: both parts stay identical
        sumG  += s_red[1 - p][t0][1];
        sumGT += s_red[1 - p][t0][2];

        // full gradients (dc + reg + positivity) and GD update (computed redundantly
        // and identically by both parity threads)
        float gA = sumA + rlA * (A - pA) + (A  < 0.0f ? 2.0f * A  : 0.0f);
        float gk = fmaf(tz, sumG, -sumGT) + rlk * (k - pk) + (k  < 0.0f ? 2.0f * k  : 0.0f);
        float gt = k * sumG + rlt * (tz - pt) + (tz < 0.0f ? 2.0f * tz : 0.0f);
        A  -= 0.1f * gA;
        k  -= 0.1f * gk;
        tz -= 0.1f * gt;

        __syncthreads();   // s_ex reused next iteration
    }

    if (p == 0) {
        out[v]        = A;
        out[NV + v]   = k;
        out[2*NV + v] = tz;
    }
}

// ---------------- launch ----------------
extern "C" void kernel_launch(void* const* d_in, const int* in_sizes, int n_in,
                              void* d_out, int out_size) {
    const float* ctc   = (const float*)d_in[0];   // (1,128,128,64)
    const float* aif   = (const float*)d_in[1];   // (1,1,1,64)
    const float* time_ = (const float*)d_in[2];   // (64,)
    // d_in[3] = seg (unused by the reference objective)
    const float* eta   = (const float*)d_in[4];   // (1,3,128,128)
    const float* lam   = (const float*)d_in[5];   // (1,)
    float* out = (float*)d_out;                   // (1,3,128,128)

    k_static <<<1, 576>>>(aif, time_);
    k_voxprep<<<64, 256>>>(ctc, eta);
    k_consts <<<1, 64>>>(lam);
    k_main   <<<128, 256>>>(eta, out);
}

// round 15
// speedup vs baseline: 1.3573x; 1.3573x over previous
#include <cuda_runtime.h>
#include <cuda_bf16.h>

#define NV 16384   // 128*128 voxels
#define NT 64      // time samples
typedef unsigned long long ULL;

// ---------------- device scratch (static, allocation-free) ----------------
__device__ float g_ctcdc[NT * NV];                 // [m][voxel], coalesced
__device__ __align__(16) float g_aifpad[576];      // phys[63+i] = aif_os[i], zero pad
__device__ __align__(16) float g_tsh[512];
__device__ float g_partCdc[64];
__device__ float g_partCnn[3 * 64];
__device__ float g_consts[4];                      // rscale, 2*sp_lam/C_nn[0..2]

// jax.image.resize(method='linear') upsample 64->512: half-pixel centers,
// renormalized (clamped) edges.
__device__ __forceinline__ float interp64(const float* __restrict__ x, int o) {
    float p = (o + 0.5f) * 0.125f - 0.5f;
    if (p <= 0.0f)  return x[0];
    if (p >= 63.0f) return x[63];
    int i = (int)p;              // p > 0 -> trunc == floor
    float f = p - (float)i;
    return (1.0f - f) * x[i] + f * x[i + 1];
}

// ---------------- kernel A: static 1-D tables ----------------
__global__ void k_static(const float* __restrict__ aif, const float* __restrict__ time_) {
    int o = threadIdx.x;                 // 576 threads
    g_aifpad[o] = 0.0f;
    __syncthreads();
    if (o < 512) {
        float ab = (aif[0] + aif[1] + aif[2] + aif[3] + aif[4]) / 5.0f;
        g_aifpad[63 + o] = interp64(aif, o) - ab;
        float t16 = interp64(time_, 16);           // t_os[NEG_SHIFT]
        g_tsh[o] = interp64(time_, o) - t16;
    }
}

// ---------------- kernel B: per-voxel ctc_dc + partial reductions ----------------
__global__ void k_voxprep(const float* __restrict__ ctc, const float* __restrict__ eta) {
    int v = blockIdx.x * 256 + threadIdx.x;
    float c[NT];
    const float4* p4 = reinterpret_cast<const float4*>(ctc) + (size_t)v * 16;
#pragma unroll
    for (int i = 0; i < 16; ++i) {
        float4 q = p4[i];
        c[4*i+0] = q.x; c[4*i+1] = q.y; c[4*i+2] = q.z; c[4*i+3] = q.w;
    }
    float base = (c[0] + c[1] + c[2] + c[3] + c[4]) / 5.0f;
    float s2;
    {
        float cd = c[0] - base;              // m = 0 : clamped edge sample
        g_ctcdc[v] = cd;
        s2 = cd * cd;
    }
#pragma unroll
    for (int m = 1; m < NT; ++m) {           // interior: 0.4375*c[m-1] + 0.5625*c[m]
        float cd = 0.4375f * c[m-1] + 0.5625f * c[m] - base;
        g_ctcdc[m * NV + v] = cd;
        s2 += cd * cd;
    }
    float e0 = eta[v], e1 = eta[NV + v], e2 = eta[2*NV + v];
    __shared__ float4 sm[256];
    sm[threadIdx.x] = make_float4(s2, e0*e0, e1*e1, e2*e2);
    __syncthreads();
    for (int s = 128; s > 0; s >>= 1) {      // fixed-order tree -> deterministic
        if (threadIdx.x < s) {
            float4 a = sm[threadIdx.x], b = sm[threadIdx.x + s];
            sm[threadIdx.x] = make_float4(a.x+b.x, a.y+b.y, a.z+b.z, a.w+b.w);
        }
        __syncthreads();
    }
    if (threadIdx.x == 0) {
        float4 r = sm[0];
        g_partCdc[blockIdx.x]        = r.x;
        g_partCnn[blockIdx.x]        = r.y;
        g_partCnn[64  + blockIdx.x]  = r.z;
        g_partCnn[128 + blockIdx.x]  = r.w;
    }
}

// ---------------- kernel C: final reduce + constants ----------------
__global__ void k_consts(const float* __restrict__ lam) {
    int t = threadIdx.x;                     // 64 threads
    __shared__ float4 sm[64];
    sm[t] = make_float4(g_partCdc[t], g_partCnn[t], g_partCnn[64 + t], g_partCnn[128 + t]);
    __syncthreads();
    for (int s = 32; s > 0; s >>= 1) {
        if (t < s) {
            float4 a = sm[t], b = sm[t + s];
            sm[t] = make_float4(a.x+b.x, a.y+b.y, a.z+b.z, a.w+b.w);
        }
        __syncthreads();
    }
    if (t == 0) {
        float Cdc = sm[0].x;
        float x = lam[0];
        float sp = fmaxf(x, 0.0f) + log1pf(expf(-fabsf(x)));   // stable softplus
        g_consts[0] = 0.25f / Cdc;             // r[m] = (est/8 - cd) * 2/(8*Cdc)
        g_consts[1] = 2.0f * sp / sm[0].y;
        g_consts[2] = 2.0f * sp / sm[0].z;
        g_consts[3] = 2.0f * sp / sm[0].w;
    }
}

// ---------------- packed fp32x2 + MUFU helpers (sm_103a) ----------------
__device__ __forceinline__ ULL pack2(float lo, float hi) {
    ULL r; asm("mov.b64 %0, {%1, %2};" : "=l"(r) : "f"(lo), "f"(hi)); return r;
}
__device__ __forceinline__ float2 unpack2(ULL v) {
    float2 r; asm("mov.b64 {%0, %1}, %2;" : "=f"(r.x), "=f"(r.y) : "l"(v)); return r;
}
__device__ __forceinline__ void ffma2(ULL& d, ULL a, ULL b) {
    asm("fma.rn.f32x2 %0, %1, %2, %0;" : "+l"(d) : "l"(a), "l"(b));
}
__device__ __forceinline__ float ex2f(float x) {
    float y; asm("ex2.approx.f32 %0, %1;" : "=f"(y) : "f"(x)); return y;
}
__device__ __forceinline__ float rcpf(float x) {
    float y; asm("rcp.approx.f32 %0, %1;" : "=f"(y) : "f"(x)); return y;
}

// ---------------- kernel D: 10 GD iterations, 2 threads per voxel ----------------
// FORWARD (R12-verified shape): row-parity split, thread p owns rows m=2*lm+p
// (acc = 32 packed regs), per-octet loop.  Sigmoids via one ex2 per octet +
// geometric chain e_{l+1} = e_l * exp(k/8) (tsh is exactly (l-16)/8 on the
// interior).  The clamped octet lb=504 uses the exact per-lane path.
// step[l]: bitwise 1.0f for l>=17, 0.5f at l=16 (sigma(500*tsh) in fp32) ->
// no table, one lane-0 fixup.
// ADJOINT: octet-parity split, DIAGONAL windows (t = m-M0-2j at float base
// 56-8p+8t feeds up to NJ octet accumulators; 576 window loads instead of
// 2288); rm as 64 float regs, packed per-use; exact per-lane ex2 sigmoids
// (handles the clamped lanes for free).
__global__ __launch_bounds__(256, 1)
void k_main(const float* __restrict__ eta_in, float* __restrict__ out) {
    __shared__ __align__(16) float s_aif[576];
    __shared__ __align__(16) float s_tsh[512];
    __shared__ float s_ex[128 * 65];     // [t0][m], padded: conflict-free both axes
    __shared__ float s_red[2][128][4];   // partial gradient sums
    __shared__ float s_c[4];
    int tid = threadIdx.x;
    for (int i = tid; i < 576; i += 256) s_aif[i] = g_aifpad[i];
    for (int i = tid; i < 512; i += 256) s_tsh[i] = g_tsh[i];
    if (tid < 4) s_c[tid] = g_consts[tid];
    __syncthreads();

    const int t0 = tid & 127;
    const int p  = tid >> 7;
    const int v  = blockIdx.x * 128 + t0;

    // adjoint diagonal windows: float base 56-8p+8t -> ULL base 28-4p+4t
    const ULL*   wbA  = reinterpret_cast<const ULL*>(s_aif) + 28 - 4 * p;
    const float* tshp = s_tsh + 8 * p;       // adjoint octet tables

    float pA = eta_in[v], pk = eta_in[NV + v], pt = eta_in[2*NV + v];
    float A = pA, k = pk, tz = pt;
    const float rscale = s_c[0], rlA = s_c[1], rlk = s_c[2], rlt = s_c[3];

#pragma unroll 1
    for (int it = 0; it < 10; ++it) {
        const float kl2   = k * 1.4426950408889634f;   // k*log2(e)
        const float c0k   = kl2 * tz;                  // e = ex2(kl2*tsh - c0k)
        const float ratio = ex2f(kl2 * 0.125f);        // exp(k/8)

        // ========== forward: rows m = 2*lm + p ==========
        ULL acc2[32];
#pragma unroll
        for (int lm = 0; lm < 32; ++lm) acc2[lm] = 0ULL;

#pragma unroll
        for (int g = 0; g < 8; ++g) {
            const int NO = (g == 7) ? 5 : 8;  // geometric octets; lb=504 handled below
#pragma unroll 1
            for (int q = 0; q < NO; ++q) {
                const int lb = 16 + 64 * g + 8 * q;
                // sigmoid via geometric exp chain (tsh linear on interior)
                float tshb = (float)(8 * g + q);        // (lb-16)/8
                float e = ex2f(fmaf(kl2, tshb, -c0k));
                float irv[8];
#pragma unroll
                for (int i = 0; i < 8; ++i) {
                    float s = rcpf(1.0f + e);
                    irv[i] = A * s;
                    e *= ratio;
                }
                if (g == 0) {                           // lane l=16 has step=0.5
                    if (q == 0) irv[0] *= 0.5f;
                }
                ULL I0 = pack2(irv[7], irv[6]);   // lowest window float = l = lb+7
                ULL I1 = pack2(irv[5], irv[4]);
                ULL I2 = pack2(irv[3], irv[2]);
                ULL I3 = pack2(irv[1], irv[0]);
                const ulonglong2* wf =
                    reinterpret_cast<const ulonglong2*>(s_aif + (72 + 8 * p - lb));
#pragma unroll
                for (int lm = 4 * g; lm < 32; ++lm) {
                    ulonglong2 qa = wf[4 * lm];
                    ulonglong2 qb = wf[4 * lm + 1];
                    ffma2(acc2[lm], I0, qa.x);
                    ffma2(acc2[lm], I1, qa.y);
                    ffma2(acc2[lm], I2, qb.x);
                    ffma2(acc2[lm], I3, qb.y);
                }
            }
        }
        {   // last octet lb=504 (clamped tsh on lanes 4-7): exact per-lane path
            const int lb = 504;
            float4 ts0 = *reinterpret_cast<const float4*>(&s_tsh[lb]);
            float4 ts1 = *reinterpret_cast<const float4*>(&s_tsh[lb + 4]);
            float tshv[8] = {ts0.x,ts0.y,ts0.z,ts0.w,ts1.x,ts1.y,ts1.z,ts1.w};
            float irv[8];
#pragma unroll
            for (int i = 0; i < 8; ++i) {
                float e = ex2f(fmaf(kl2, tshv[i], -c0k));
                irv[i] = A * rcpf(1.0f + e);
            }
            ULL I0 = pack2(irv[7], irv[6]);
            ULL I1 = pack2(irv[5], irv[4]);
            ULL I2 = pack2(irv[3], irv[2]);
            ULL I3 = pack2(irv[1], irv[0]);
            const ulonglong2* wf =
                reinterpret_cast<const ulonglong2*>(s_aif + (72 + 8 * p - lb));
#pragma unroll
            for (int lm = 28; lm < 32; ++lm) {
                ulonglong2 qa = wf[4 * lm];
                ulonglong2 qb = wf[4 * lm + 1];
                ffma2(acc2[lm], I0, qa.x);
                ffma2(acc2[lm], I1, qa.y);
                ffma2(acc2[lm], I2, qb.x);
                ffma2(acc2[lm], I3, qb.y);
            }
        }

        // residual for my rows (complete, no combine needed)
#pragma unroll
        for (int lm = 0; lm < 32; ++lm) {
            const int m = 2 * lm + p;
            float2 u = unpack2(acc2[lm]);
            float full = u.x + u.y;
            float cd = __ldg(&g_ctcdc[m * NV + v]);      // L1-resident after iter 1
            s_ex[t0 * 65 + m] = (0.125f * full - cd) * rscale;
        }
        __syncthreads();

        // rm into registers (acc2 dead -> regs free)
        float rmv[NT];
#pragma unroll
        for (int m = 0; m < NT; ++m) rmv[m] = s_ex[t0 * 65 + m];

        // ========== adjoint: diagonal windows, my parity's octets ==========
        float sumA = 0.0f, sumG = 0.0f, sumGT = 0.0f;
#pragma unroll
        for (int g = 0; g < 8; ++g) {
            const int M0 = 8 * g;
            const int NJ = (g == 7) ? 3 : 4;
            const int N  = 64 - M0;
            ULL w[4][4];
#pragma unroll
            for (int j = 0; j < 4; ++j)
#pragma unroll
                for (int q = 0; q < 4; ++q) w[j][q] = 0ULL;

#pragma unroll
            for (int t = 0; t < N; ++t) {
                ulonglong2 qa = *reinterpret_cast<const ulonglong2*>(wbA + 4 * t);
                ulonglong2 qb = *reinterpret_cast<const ulonglong2*>(wbA + 4 * t + 2);
#pragma unroll
                for (int j = 0; j < 4; ++j) {
                    if (j < NJ) {                       // compile-time
                        const int n = t + 2 * j;
                        if (n < N) {                    // compile-time
                            float r = rmv[M0 + n];
                            ULL r2 = pack2(r, r);
                            ffma2(w[j][0], r2, qa.x);
                            ffma2(w[j][1], r2, qa.y);
                            ffma2(w[j][2], r2, qb.x);
                            ffma2(w[j][3], r2, qb.y);
                        }
                    }
                }
            }
#pragma unroll
            for (int j = 0; j < 4; ++j) {
                if (j < NJ) {
                    float2 u0 = unpack2(w[j][0]), u1 = unpack2(w[j][1]),
                           u2 = unpack2(w[j][2]), u3 = unpack2(w[j][3]);
                    float wv[8] = {u3.y, u3.x, u2.y, u2.x, u1.y, u1.x, u0.y, u0.x};
                    const int lbx = 16 + 64 * g + 16 * j;   // +8p via tshp
                    float4 ts0 = *reinterpret_cast<const float4*>(&tshp[lbx]);
                    float4 ts1 = *reinterpret_cast<const float4*>(&tshp[lbx + 4]);
                    float tshv[8] = {ts0.x,ts0.y,ts0.z,ts0.w,ts1.x,ts1.y,ts1.z,ts1.w};
#pragma unroll
                    for (int i = 0; i < 8; ++i) {
                        float tshl = tshv[i];
                        float e = ex2f(fmaf(kl2, tshl, -c0k));
                        float s = rcpf(1.0f + e);
                        float u = wv[i];
                        if (g == 0 && j == 0 && i == 0)   // l=16 lane (p=0 only): step=0.5
                            u *= (p == 0) ? 0.5f : 1.0f;
                        sumA = fmaf(u, s, sumA);          // dir/dA = s*step
                        float nms = fmaf(-s, s, s);       // s*(1-s)
                        float gg  = u * A * nms;
                        sumG += gg;
                        sumGT = fmaf(gg, tshl, sumGT);
                    }
                }
            }
        }

        // ---------- combine partial sums across the two parts ----------
        s_red[p][t0][0] = sumA; s_red[p][t0][1] = sumG; s_red[p][t0][2] = sumGT;
        __syncthreads();
        sumA  += s_red[1 - p][t0][0];   // a+b == b+a bitwise: both parts stay identical
        sumG  += s_red[1 - p][t0][1];
        sumGT += s_red[1 - p][t0][2];

        // full gradients (dc + reg + positivity) and GD update (computed redundantly
        // and identically by both parity threads)
        float gA = sumA + rlA * (A - pA) + (A  < 0.0f ? 2.0f * A  : 0.0f);
        float gk = fmaf(tz, sumG, -sumGT) + rlk * (k - pk) + (k  < 0.0f ? 2.0f * k  : 0.0f);
        float gt = k * sumG + rlt * (tz - pt) + (tz < 0.0f ? 2.0f * tz : 0.0f);
        A  -= 0.1f * gA;
        k  -= 0.1f * gk;
        tz -= 0.1f * gt;
    }

    if (p == 0) {
        out[v]        = A;
        out[NV + v]   = k;
        out[2*NV + v] = tz;
    }
}

// ---------------- launch ----------------
extern "C" void kernel_launch(void* const* d_in, const int* in_sizes, int n_in,
                              void* d_out, int out_size) {
    const float* ctc   = (const float*)d_in[0];   // (1,128,128,64)
    const float* aif   = (const float*)d_in[1];   // (1,1,1,64)
    const float* time_ = (const float*)d_in[2];   // (64,)
    // d_in[3] = seg (unused by the reference objective)
    const float* eta   = (const float*)d_in[4];   // (1,3,128,128)
    const float* lam   = (const float*)d_in[5];   // (1,)
    float* out = (float*)d_out;                   // (1,3,128,128)

    k_static <<<1, 576>>>(aif, time_);
    k_voxprep<<<64, 256>>>(ctc, eta);
    k_consts <<<1, 64>>>(lam);
    k_main   <<<128, 256>>>(eta, out);
}

// round 16
// speedup vs baseline: 3.3087x; 2.4377x over previous
#include <cuda_runtime.h>
#include <cuda_bf16.h>

#define NV 16384   // 128*128 voxels
#define NT 64      // time samples
typedef unsigned long long ULL;

// ---------------- device scratch (static, allocation-free) ----------------
__device__ float g_ctcdc[NT * NV];                 // [m][voxel], coalesced
__device__ __align__(16) float g_aifpad[576];      // phys[63+i] = aif_os[i], zero pad
__device__ __align__(16) float g_tsh[512];
__device__ float g_partCdc[64];
__device__ float g_partCnn[3 * 64];
__device__ float g_consts[4];                      // rscale, 2*sp_lam/C_nn[0..2]

// jax.image.resize(method='linear') upsample 64->512: half-pixel centers,
// renormalized (clamped) edges.
__device__ __forceinline__ float interp64(const float* __restrict__ x, int o) {
    float p = (o + 0.5f) * 0.125f - 0.5f;
    if (p <= 0.0f)  return x[0];
    if (p >= 63.0f) return x[63];
    int i = (int)p;              // p > 0 -> trunc == floor
    float f = p - (float)i;
    return (1.0f - f) * x[i] + f * x[i + 1];
}

// ---------------- kernel A: static 1-D tables ----------------
__global__ void k_static(const float* __restrict__ aif, const float* __restrict__ time_) {
    int o = threadIdx.x;                 // 576 threads
    g_aifpad[o] = 0.0f;
    __syncthreads();
    if (o < 512) {
        float ab = (aif[0] + aif[1] + aif[2] + aif[3] + aif[4]) / 5.0f;
        g_aifpad[63 + o] = interp64(aif, o) - ab;
        float t16 = interp64(time_, 16);           // t_os[NEG_SHIFT]
        g_tsh[o] = interp64(time_, o) - t16;
    }
}

// ---------------- kernel B: per-voxel ctc_dc + partial reductions ----------------
__global__ void k_voxprep(const float* __restrict__ ctc, const float* __restrict__ eta) {
    int v = blockIdx.x * 256 + threadIdx.x;
    float c[NT];
    const float4* p4 = reinterpret_cast<const float4*>(ctc) + (size_t)v * 16;
#pragma unroll
    for (int i = 0; i < 16; ++i) {
        float4 q = p4[i];
        c[4*i+0] = q.x; c[4*i+1] = q.y; c[4*i+2] = q.z; c[4*i+3] = q.w;
    }
    float base = (c[0] + c[1] + c[2] + c[3] + c[4]) / 5.0f;
    float s2;
    {
        float cd = c[0] - base;              // m = 0 : clamped edge sample
        g_ctcdc[v] = cd;
        s2 = cd * cd;
    }
#pragma unroll
    for (int m = 1; m < NT; ++m) {           // interior: 0.4375*c[m-1] + 0.5625*c[m]
        float cd = 0.4375f * c[m-1] + 0.5625f * c[m] - base;
        g_ctcdc[m * NV + v] = cd;
        s2 += cd * cd;
    }
    float e0 = eta[v], e1 = eta[NV + v], e2 = eta[2*NV + v];
    __shared__ float4 sm[256];
    sm[threadIdx.x] = make_float4(s2, e0*e0, e1*e1, e2*e2);
    __syncthreads();
    for (int s = 128; s > 0; s >>= 1) {      // fixed-order tree -> deterministic
        if (threadIdx.x < s) {
            float4 a = sm[threadIdx.x], b = sm[threadIdx.x + s];
            sm[threadIdx.x] = make_float4(a.x+b.x, a.y+b.y, a.z+b.z, a.w+b.w);
        }
        __syncthreads();
    }
    if (threadIdx.x == 0) {
        float4 r = sm[0];
        g_partCdc[blockIdx.x]        = r.x;
        g_partCnn[blockIdx.x]        = r.y;
        g_partCnn[64  + blockIdx.x]  = r.z;
        g_partCnn[128 + blockIdx.x]  = r.w;
    }
}

// ---------------- kernel C: final reduce + constants ----------------
__global__ void k_consts(const float* __restrict__ lam) {
    int t = threadIdx.x;                     // 64 threads
    __shared__ float4 sm[64];
    sm[t] = make_float4(g_partCdc[t], g_partCnn[t], g_partCnn[64 + t], g_partCnn[128 + t]);
    __syncthreads();
    for (int s = 32; s > 0; s >>= 1) {
        if (t < s) {
            float4 a = sm[t], b = sm[t + s];
            sm[t] = make_float4(a.x+b.x, a.y+b.y, a.z+b.z, a.w+b.w);
        }
        __syncthreads();
    }
    if (t == 0) {
        float Cdc = sm[0].x;
        float x = lam[0];
        float sp = fmaxf(x, 0.0f) + log1pf(expf(-fabsf(x)));   // stable softplus
        g_consts[0] = 0.25f / Cdc;             // r[m] = (est/8 - cd) * 2/(8*Cdc)
        g_consts[1] = 2.0f * sp / sm[0].y;
        g_consts[2] = 2.0f * sp / sm[0].z;
        g_consts[3] = 2.0f * sp / sm[0].w;
    }
}

// ---------------- packed fp32x2 + MUFU helpers (sm_103a) ----------------
__device__ __forceinline__ ULL pack2(float lo, float hi) {
    ULL r; asm("mov.b64 %0, {%1, %2};" : "=l"(r) : "f"(lo), "f"(hi)); return r;
}
__device__ __forceinline__ float2 unpack2(ULL v) {
    float2 r; asm("mov.b64 {%0, %1}, %2;" : "=f"(r.x), "=f"(r.y) : "l"(v)); return r;
}
__device__ __forceinline__ void ffma2(ULL& d, ULL a, ULL b) {
    asm("fma.rn.f32x2 %0, %1, %2, %0;" : "+l"(d) : "l"(a), "l"(b));
}
__device__ __forceinline__ float ex2f(float x) {
    float y; asm("ex2.approx.f32 %0, %1;" : "=f"(y) : "f"(x)); return y;
}
__device__ __forceinline__ float rcpf(float x) {
    float y; asm("rcp.approx.f32 %0, %1;" : "=f"(y) : "f"(x)); return y;
}

// ---------------- kernel D: 10 GD iterations, 2 threads per voxel ----------------
// Structure = R12 (verified non-spilling: sequential octet loops both passes).
// Sigmoid math = R14 (verified correct): forward uses one ex2 per octet + the
// geometric chain e_{l+1} = e_l*exp(k/8) (tsh is exactly (l-16)/8 interior);
// clamped octet lb=504 uses the per-lane table path.  step[l] is analytically
// bitwise 1.0f for l>=17 and 0.5f at l=16 -> no step table, one lane fixup.
// Adjoint: R12's sequential-j loops (w0..w3 only live), rm as 64 float regs,
// per-lane ex2 sigmoid from the tsh table (handles clamped lanes for free).
__global__ __launch_bounds__(256, 1)
void k_main(const float* __restrict__ eta_in, float* __restrict__ out) {
    __shared__ __align__(16) float s_aif[576];
    __shared__ __align__(16) float s_tsh[512];
    __shared__ float s_ex[128 * 65];     // [t0][m], padded: conflict-free both axes
    __shared__ float s_red[2][128][4];   // partial gradient sums
    __shared__ float s_c[4];
    int tid = threadIdx.x;
    for (int i = tid; i < 576; i += 256) s_aif[i] = g_aifpad[i];
    for (int i = tid; i < 512; i += 256) s_tsh[i] = g_tsh[i];
    if (tid < 4) s_c[tid] = g_consts[tid];
    __syncthreads();

    const int t0 = tid & 127;
    const int p  = tid >> 7;
    const int v  = blockIdx.x * 128 + t0;

    float pA = eta_in[v], pk = eta_in[NV + v], pt = eta_in[2*NV + v];
    float A = pA, k = pk, tz = pt;
    const float rscale = s_c[0], rlA = s_c[1], rlk = s_c[2], rlt = s_c[3];

#pragma unroll 1
    for (int it = 0; it < 10; ++it) {
        const float kl2   = k * 1.4426950408889634f;   // k*log2(e)
        const float c0k   = kl2 * tz;                  // e = ex2(kl2*tsh - c0k)
        const float ratio = ex2f(kl2 * 0.125f);        // exp(k/8)

        // ========== forward: rows m = 2*lm + p, all octets (R12 shape) ==========
        ULL acc2[32];
#pragma unroll
        for (int lm = 0; lm < 32; ++lm) acc2[lm] = 0ULL;

#pragma unroll
        for (int g = 0; g < 8; ++g) {
            const int NO = (g == 7) ? 5 : 8;  // geometric octets; lb=504 below
#pragma unroll 1
            for (int q = 0; q < NO; ++q) {
                const int lb = 16 + 64 * g + 8 * q;
                // sigmoid via geometric exp chain (tsh exactly (l-16)/8 here)
                float tshb = (float)(8 * g + q);        // (lb-16)/8
                float e = ex2f(fmaf(kl2, tshb, -c0k));
                float irv[8];
#pragma unroll
                for (int i = 0; i < 8; ++i) {
                    irv[i] = A * rcpf(1.0f + e);
                    e *= ratio;
                }
                if (g == 0 && q == 0) irv[0] *= 0.5f;   // l=16: step = 0.5 exactly
                ULL I0 = pack2(irv[7], irv[6]);   // lowest window float = l = lb+7
                ULL I1 = pack2(irv[5], irv[4]);
                ULL I2 = pack2(irv[3], irv[2]);
                ULL I3 = pack2(irv[1], irv[0]);
                const ulonglong2* wf =
                    reinterpret_cast<const ulonglong2*>(s_aif + (72 + 8 * p - lb));
#pragma unroll
                for (int lm = 4 * g; lm < 32; ++lm) {
                    ulonglong2 qa = wf[4 * lm];
                    ulonglong2 qb = wf[4 * lm + 1];
                    ffma2(acc2[lm], I0, qa.x);
                    ffma2(acc2[lm], I1, qa.y);
                    ffma2(acc2[lm], I2, qb.x);
                    ffma2(acc2[lm], I3, qb.y);
                }
            }
        }
        {   // last octet lb=504 (clamped tsh on top lanes): exact per-lane path
            const int lb = 504;
            float4 ts0 = *reinterpret_cast<const float4*>(&s_tsh[lb]);
            float4 ts1 = *reinterpret_cast<const float4*>(&s_tsh[lb + 4]);
            float tshv[8] = {ts0.x,ts0.y,ts0.z,ts0.w,ts1.x,ts1.y,ts1.z,ts1.w};
            float irv[8];
#pragma unroll
            for (int i = 0; i < 8; ++i) {
                float e = ex2f(fmaf(kl2, tshv[i], -c0k));
                irv[i] = A * rcpf(1.0f + e);
            }
            ULL I0 = pack2(irv[7], irv[6]);
            ULL I1 = pack2(irv[5], irv[4]);
            ULL I2 = pack2(irv[3], irv[2]);
            ULL I3 = pack2(irv[1], irv[0]);
            const ulonglong2* wf =
                reinterpret_cast<const ulonglong2*>(s_aif + (72 + 8 * p - lb));
#pragma unroll
            for (int lm = 28; lm < 32; ++lm) {
                ulonglong2 qa = wf[4 * lm];
                ulonglong2 qb = wf[4 * lm + 1];
                ffma2(acc2[lm], I0, qa.x);
                ffma2(acc2[lm], I1, qa.y);
                ffma2(acc2[lm], I2, qb.x);
                ffma2(acc2[lm], I3, qb.y);
            }
        }

        // residual for my rows (complete, no combine needed)
#pragma unroll
        for (int lm = 0; lm < 32; ++lm) {
            const int m = 2 * lm + p;
            float2 u = unpack2(acc2[lm]);
            float full = u.x + u.y;
            float cd = __ldg(&g_ctcdc[m * NV + v]);      // L1-resident after iter 1
            s_ex[t0 * 65 + m] = (0.125f * full - cd) * rscale;
        }
        __syncthreads();

        // rm into registers (acc2 dead -> regs free)
        float rmv[NT];
#pragma unroll
        for (int m = 0; m < NT; ++m) rmv[m] = s_ex[t0 * 65 + m];

        // ========== adjoint (R12 shape): my parity's octets, sequential j ==========
        float sumA = 0.0f, sumG = 0.0f, sumGT = 0.0f;
#pragma unroll
        for (int g = 0; g < 8; ++g) {
            const int M0 = 8 * g;
            const int NJ = (g == 7) ? 3 : 4;
#pragma unroll 1
            for (int j = 0; j < NJ; ++j) {
                const int lb = 16 + 64 * g + 16 * j + 8 * p;
                ULL w0 = 0, w1 = 0, w2 = 0, w3 = 0;
                const int base = 56 - 16 * j - 8 * p;    // = 72 + 8*M0 - lb >= 0
                const ulonglong2* ap2 =
                    reinterpret_cast<const ulonglong2*>(s_aif + base);
#pragma unroll
                for (int m = M0; m < 64; ++m) {
                    ULL rm2 = pack2(rmv[m], rmv[m]);
                    ulonglong2 qa = ap2[2 * (m - M0)];
                    ulonglong2 qb = ap2[2 * (m - M0) + 1];
                    ffma2(w0, rm2, qa.x);
                    ffma2(w1, rm2, qa.y);
                    ffma2(w2, rm2, qb.x);
                    ffma2(w3, rm2, qb.y);
                }
                float2 u0 = unpack2(w0), u1 = unpack2(w1),
                       u2 = unpack2(w2), u3 = unpack2(w3);
                float wv[8] = {u3.y, u3.x, u2.y, u2.x, u1.y, u1.x, u0.y, u0.x};
                float4 ts0 = *reinterpret_cast<const float4*>(&s_tsh[lb]);
                float4 ts1 = *reinterpret_cast<const float4*>(&s_tsh[lb + 4]);
                float tshv[8] = {ts0.x,ts0.y,ts0.z,ts0.w,ts1.x,ts1.y,ts1.z,ts1.w};
#pragma unroll
                for (int i = 0; i < 8; ++i) {
                    float tshl = tshv[i];
                    float e = ex2f(fmaf(kl2, tshl, -c0k));
                    float s = rcpf(1.0f + e);
                    float u = wv[i];
                    if (g == 0 && j == 0 && i == 0)      // l=16 lane exists only at p=0
                        u *= (p == 0) ? 0.5f : 1.0f;
                    sumA = fmaf(u, s, sumA);             // dir/dA = s*step
                    float nms = fmaf(-s, s, s);          // s*(1-s)
                    float gg  = u * A * nms;
                    sumG += gg;
                    sumGT = fmaf(gg, tshl, sumGT);
                }
            }
        }

        // ---------- combine partial sums across the two parts ----------
        s_red[p][t0][0] = sumA; s_red[p][t0][1] = sumG; s_red[p][t0][2] = sumGT;
        __syncthreads();
        sumA  += s_red[1 - p][t0][0];   // a+b == b+a bitwise: both parts stay identical
        sumG  += s_red[1 - p][t0][1];
        sumGT += s_red[1 - p][t0][2];

        // full gradients (dc + reg + positivity) and GD update (computed redundantly
        // and identically by both parity threads)
        float gA = sumA + rlA * (A - pA) + (A  < 0.0f ? 2.0f * A  : 0.0f);
        float gk = fmaf(tz, sumG, -sumGT) + rlk * (k - pk) + (k  < 0.0f ? 2.0f * k  : 0.0f);
        float gt = k * sumG + rlt * (tz - pt) + (tz < 0.0f ? 2.0f * tz : 0.0f);
        A  -= 0.1f * gA;
        k  -= 0.1f * gk;
        tz -= 0.1f * gt;
    }

    if (p == 0) {
        out[v]        = A;
        out[NV + v]   = k;
        out[2*NV + v] = tz;
    }
}

// ---------------- launch ----------------
extern "C" void kernel_launch(void* const* d_in, const int* in_sizes, int n_in,
                              void* d_out, int out_size) {
    const float* ctc   = (const float*)d_in[0];   // (1,128,128,64)
    const float* aif   = (const float*)d_in[1];   // (1,1,1,64)
    const float* time_ = (const float*)d_in[2];   // (64,)
    // d_in[3] = seg (unused by the reference objective)
    const float* eta   = (const float*)d_in[4];   // (1,3,128,128)
    const float* lam   = (const float*)d_in[5];   // (1,)
    float* out = (float*)d_out;                   // (1,3,128,128)

    k_static <<<1, 576>>>(aif, time_);
    k_voxprep<<<64, 256>>>(ctc, eta);
    k_consts <<<1, 64>>>(lam);
    k_main   <<<128, 256>>>(eta, out);
}